// round 4
// baseline (speedup 1.0000x reference)
#include <cuda_runtime.h>
#include <cuda_bf16.h>
#include <cstdint>
#include <math.h>

// ===========================================================================
// Net_6983616823390 — binarized MLP (sm_103, mma.sync path)
//  L1 : bf16 HMMA, K=6144 (x hi|lo split)  -> step bits (s8)
//  L2-4: int8 IMMA (exact), K=2048          -> step bits (s8) / fp32 h4
//  L5 : fp32 SIMT
//  cp.async 3-stage pipelines, fused alpha/bias/relu/step + mean partials.
// ===========================================================================

#define B_ROWS 8192
#define HDIM   2000
#define HPAD   2048
#define DIN    3072
#define K1PAD  6144

#define RED_BLOCKS 512
#define RED_THREADS 256
#define GPARTS 1024

#define RS      80          // smem row stride bytes (64B data + 16B pad)
#define STGB    20480       // bytes per stage: A(128*80) + B(128*80)
#define SMEM_DYN (3 * STGB + 2048)   // stages + double smr[256]

__device__ float  d_scales[8];
__device__ double d_partials[8][GPARTS];

__device__ __align__(16) __nv_bfloat16 g_xs  [(size_t)B_ROWS * K1PAD];
__device__ __align__(16) __nv_bfloat16 g_sw1 [(size_t)HPAD * K1PAD];
__device__ __align__(16) int8_t g_sw2 [(size_t)HPAD * HPAD];
__device__ __align__(16) int8_t g_sw3 [(size_t)HPAD * HPAD];
__device__ __align__(16) int8_t g_sw4 [(size_t)HPAD * HPAD];
__device__ __align__(16) int8_t g_stepA[(size_t)B_ROWS * HPAD];
__device__ __align__(16) int8_t g_stepB[(size_t)B_ROWS * HPAD];
__device__ __align__(16) float g_h4[(size_t)B_ROWS * HDIM];

__device__ __forceinline__ uint32_t smem_u32(const void* p) {
    uint32_t a;
    asm("{ .reg .u64 t; cvta.to.shared.u64 t, %1; cvt.u32.u64 %0, t; }" : "=r"(a) : "l"(p));
    return a;
}
__device__ __forceinline__ void ldm_x4(uint32_t* r, uint32_t addr) {
    asm volatile("ldmatrix.sync.aligned.m8n8.x4.shared.b16 {%0,%1,%2,%3}, [%4];"
        : "=r"(r[0]), "=r"(r[1]), "=r"(r[2]), "=r"(r[3]) : "r"(addr));
}
__device__ __forceinline__ void mma_bf16(float* c, const uint32_t* a,
                                         uint32_t b0, uint32_t b1) {
    asm volatile(
        "mma.sync.aligned.m16n8k16.row.col.f32.bf16.bf16.f32 "
        "{%0,%1,%2,%3}, {%4,%5,%6,%7}, {%8,%9}, {%0,%1,%2,%3};"
        : "+f"(c[0]), "+f"(c[1]), "+f"(c[2]), "+f"(c[3])
        : "r"(a[0]), "r"(a[1]), "r"(a[2]), "r"(a[3]), "r"(b0), "r"(b1));
}
__device__ __forceinline__ void mma_s8(int* c, const uint32_t* a,
                                       uint32_t b0, uint32_t b1) {
    asm volatile(
        "mma.sync.aligned.m16n8k32.row.col.s32.s8.s8.s32 "
        "{%0,%1,%2,%3}, {%4,%5,%6,%7}, {%8,%9}, {%0,%1,%2,%3};"
        : "+r"(c[0]), "+r"(c[1]), "+r"(c[2]), "+r"(c[3])
        : "r"(a[0]), "r"(a[1]), "r"(a[2]), "r"(a[3]), "r"(b0), "r"(b1));
}
#define CP16(d, s)  asm volatile("cp.async.cg.shared.global [%0], [%1], 16;" :: "r"(d), "l"(s) : "memory")
#define CPCOMMIT()  asm volatile("cp.async.commit_group;" ::: "memory")
#define CPWAIT1()   asm volatile("cp.async.wait_group 1;" ::: "memory")

// ===========================================================================
// Deterministic reductions
// ===========================================================================
__global__ void __launch_bounds__(RED_THREADS)
reduce_abs_partial(const float* __restrict__ src, long n, int slot) {
    double s = 0.0;
    long stride = (long)gridDim.x * blockDim.x;
    for (long i = (long)blockIdx.x * blockDim.x + threadIdx.x; i < n; i += stride)
        s += (double)fabsf(src[i]);
    __shared__ double sm[RED_THREADS];
    sm[threadIdx.x] = s; __syncthreads();
    for (int o = RED_THREADS / 2; o > 0; o >>= 1) {
        if (threadIdx.x < o) sm[threadIdx.x] += sm[threadIdx.x + o];
        __syncthreads();
    }
    if (threadIdx.x == 0) d_partials[slot][blockIdx.x] = sm[0];
}
__global__ void __launch_bounds__(512)
reduce_finalize(int slot, double invn, int nparts) {
    __shared__ double sm[512];
    int t = threadIdx.x;
    double v = (t < nparts) ? d_partials[slot][t] : 0.0;
    if (t + 512 < nparts) v += d_partials[slot][t + 512];
    sm[t] = v; __syncthreads();
    for (int o = 256; o > 0; o >>= 1) {
        if (t < o) sm[t] += sm[t + o];
        __syncthreads();
    }
    if (t == 0) d_scales[slot] = (float)(sm[0] * invn);
}

// ===========================================================================
// Conversions
// ===========================================================================
__global__ void __launch_bounds__(256)
k_split_x(const float* __restrict__ x) {
    long gid = (long)blockIdx.x * blockDim.x + threadIdx.x;
    long n4 = (long)B_ROWS * DIN / 4;
    if (gid >= n4) return;
    int m = (int)(gid / (DIN / 4));
    int c = (int)(gid % (DIN / 4)) * 4;
    const float4 v = *(const float4*)&x[(long)m * DIN + c];
    float vv[4] = {v.x, v.y, v.z, v.w};
    __nv_bfloat16 hi[4], lo[4];
#pragma unroll
    for (int i = 0; i < 4; i++) {
        hi[i] = __float2bfloat16(vv[i]);
        lo[i] = __float2bfloat16(vv[i] - __bfloat162float(hi[i]));
    }
    *(uint2*)&g_xs[(long)m * K1PAD + c]       = *(uint2*)hi;
    *(uint2*)&g_xs[(long)m * K1PAD + DIN + c] = *(uint2*)lo;
}
__device__ __forceinline__ uint32_t sgn_pair(float a, float b) {
    uint32_t lo = (a > 0.f) ? 0x3F80u : ((a < 0.f) ? 0xBF80u : 0u);
    uint32_t hi = (b > 0.f) ? 0x3F80u : ((b < 0.f) ? 0xBF80u : 0u);
    return lo | (hi << 16);
}
__global__ void __launch_bounds__(256)
k_sign_w1(const float* __restrict__ W1) {
    long gid = (long)blockIdx.x * blockDim.x + threadIdx.x;
    long n2 = (long)HPAD * K1PAD / 2;
    if (gid >= n2) return;
    int r = (int)(gid / (K1PAD / 2));
    int c = (int)(gid % (K1PAD / 2)) * 2;
    uint32_t w = 0;
    if (r < HDIM) {
        int sc = (c < DIN) ? c : (c - DIN);
        w = sgn_pair(W1[(long)r * DIN + sc], W1[(long)r * DIN + sc + 1]);
    }
    *(uint32_t*)&g_sw1[(long)r * K1PAD + c] = w;
}
__global__ void __launch_bounds__(256)
k_sign_w_s8(const float* __restrict__ W, int8_t* __restrict__ dst) {
    long gid = (long)blockIdx.x * blockDim.x + threadIdx.x;
    long n4 = (long)HPAD * HPAD / 4;
    if (gid >= n4) return;
    int r = (int)(gid / (HPAD / 4));
    int c = (int)(gid % (HPAD / 4)) * 4;
    uint32_t w = 0;
    if (r < HDIM && c < HDIM) {
#pragma unroll
        for (int i = 0; i < 4; i++) {
            float v = W[(long)r * HDIM + c + i];
            uint32_t b = (v > 0.f) ? 1u : ((v < 0.f) ? 0xFFu : 0u);
            w |= b << (8 * i);
        }
    }
    *(uint32_t*)&dst[(long)r * HPAD + c] = w;
}

// ===========================================================================
// L1: bf16 HMMA GEMM, K=6144, cp.async 3-stage. Out: step bits (s8) + mean.
// ===========================================================================
__global__ void __launch_bounds__(256, 2)
gemm_l1(const __nv_bfloat16* __restrict__ A, const __nv_bfloat16* __restrict__ Bw,
        const float* __restrict__ bias, int8_t* __restrict__ stepOut,
        int sW, int slot)
{
    extern __shared__ char smem[];
    const uint32_t sbase = smem_u32(smem);
    double* smr = (double*)(smem + 3 * STGB);

    const int tid  = threadIdx.x;
    const int wid  = tid >> 5;
    const int lane = tid & 31;
    const int wm   = wid >> 2;
    const int wn   = wid & 3;
    const int brow = blockIdx.y * 128;
    const int bcol = blockIdx.x * 128;
    const int NC   = K1PAD / 32;     // 192

    const int r1 = tid >> 2,          s1 = tid & 3;
    const int r2 = (tid + 256) >> 2,  s2 = (tid + 256) & 3;
    const __nv_bfloat16* A1 = A  + (size_t)(brow + r1) * K1PAD + s1 * 8;
    const __nv_bfloat16* A2 = A  + (size_t)(brow + r2) * K1PAD + s2 * 8;
    const __nv_bfloat16* B1 = Bw + (size_t)(bcol + r1) * K1PAD + s1 * 8;
    const __nv_bfloat16* B2 = Bw + (size_t)(bcol + r2) * K1PAD + s2 * 8;
    const uint32_t dA1 = r1 * RS + s1 * 16, dA2 = r2 * RS + s2 * 16;

    const int aj = lane & 7, asel = lane >> 3;
    const uint32_t a_off = (uint32_t)((wm * 64 + aj + (asel & 1) * 8) * RS + (asel >> 1) * 16);
    const uint32_t b_off = (uint32_t)((wn * 32 + aj + (asel >> 1) * 8) * RS + (asel & 1) * 16);

    float acc[4][4][4];
#pragma unroll
    for (int i = 0; i < 4; i++)
#pragma unroll
        for (int j = 0; j < 4; j++)
#pragma unroll
            for (int q = 0; q < 4; q++) acc[i][j][q] = 0.f;

#pragma unroll
    for (int s = 0; s < 2; s++) {
        uint32_t sa = sbase + s * STGB, sb = sa + 10240;
        CP16(sa + dA1, A1 + s * 32); CP16(sa + dA2, A2 + s * 32);
        CP16(sb + dA1, B1 + s * 32); CP16(sb + dA2, B2 + s * 32);
        CPCOMMIT();
    }

    int st = 0, stn = 2;
    for (int it = 0; it < NC; it++) {
        CPWAIT1();
        __syncthreads();
        if (it + 2 < NC) {
            uint32_t sa = sbase + stn * STGB, sb = sa + 10240;
            const int c = (it + 2) * 32;
            CP16(sa + dA1, A1 + c); CP16(sa + dA2, A2 + c);
            CP16(sb + dA1, B1 + c); CP16(sb + dA2, B2 + c);
        }
        CPCOMMIT();

        const uint32_t ab = sbase + st * STGB, bb = ab + 10240;
#pragma unroll
        for (int ks = 0; ks < 2; ks++) {
            uint32_t bfr[2][4];
#pragma unroll
            for (int p = 0; p < 2; p++)
                ldm_x4(bfr[p], bb + b_off + p * 16 * RS + ks * 32);
#pragma unroll
            for (int mf = 0; mf < 4; mf++) {
                uint32_t afr[4];
                ldm_x4(afr, ab + a_off + mf * 16 * RS + ks * 32);
#pragma unroll
                for (int nf = 0; nf < 4; nf++)
                    mma_bf16(acc[mf][nf], afr,
                             bfr[nf >> 1][(nf & 1) * 2], bfr[nf >> 1][(nf & 1) * 2 + 1]);
            }
        }
        if (++st == 3) st = 0;
        if (++stn == 3) stn = 0;
    }

    const float alpha = d_scales[sW];
    double mysum = 0.0;
#pragma unroll
    for (int mf = 0; mf < 4; mf++) {
        const int m0 = brow + wm * 64 + mf * 16 + (lane >> 2);
#pragma unroll
        for (int nf = 0; nf < 4; nf++) {
            const int n = bcol + wn * 32 + nf * 8 + 2 * (lane & 3);
            const bool v0 = (n < HDIM), v1 = (n + 1 < HDIM);
            const float bv0 = v0 ? bias[n] : 0.f;
            const float bv1 = v1 ? bias[n + 1] : 0.f;
            float p00 = fmaf(alpha, acc[mf][nf][0], bv0);
            float p01 = fmaf(alpha, acc[mf][nf][1], bv1);
            float p10 = fmaf(alpha, acc[mf][nf][2], bv0);
            float p11 = fmaf(alpha, acc[mf][nf][3], bv1);
            float h00 = (v0 && p00 > 0.f) ? p00 : 0.f;
            float h01 = (v1 && p01 > 0.f) ? p01 : 0.f;
            float h10 = (v0 && p10 > 0.f) ? p10 : 0.f;
            float h11 = (v1 && p11 > 0.f) ? p11 : 0.f;
            mysum += (double)h00 + (double)h01 + (double)h10 + (double)h11;
            uchar2 q0 = make_uchar2(h00 > 0.f ? 1 : 0, h01 > 0.f ? 1 : 0);
            uchar2 q1 = make_uchar2(h10 > 0.f ? 1 : 0, h11 > 0.f ? 1 : 0);
            *(uchar2*)&stepOut[(size_t)m0 * HPAD + n] = q0;
            *(uchar2*)&stepOut[(size_t)(m0 + 8) * HPAD + n] = q1;
        }
    }
    smr[tid] = mysum;
    __syncthreads();
    for (int o = 128; o > 0; o >>= 1) {
        if (tid < o) smr[tid] += smr[tid + o];
        __syncthreads();
    }
    if (tid == 0) d_partials[slot][blockIdx.y * gridDim.x + blockIdx.x] = smr[0];
}

// ===========================================================================
// L2-4: int8 IMMA GEMM (exact), K=2048 (BK=64), cp.async 3-stage.
// ===========================================================================
__global__ void __launch_bounds__(256, 2)
gemm_s8(const int8_t* __restrict__ A, const int8_t* __restrict__ Bw,
        const float* __restrict__ bias, int8_t* __restrict__ stepOut,
        float* __restrict__ h4Out, int sA, int sW, int slot)
{
    extern __shared__ char smem[];
    const uint32_t sbase = smem_u32(smem);
    double* smr = (double*)(smem + 3 * STGB);

    const int tid  = threadIdx.x;
    const int wid  = tid >> 5;
    const int lane = tid & 31;
    const int wm   = wid >> 2;
    const int wn   = wid & 3;
    const int brow = blockIdx.y * 128;
    const int bcol = blockIdx.x * 128;
    const int NC   = HPAD / 64;      // 32

    const int r1 = tid >> 2,          s1 = tid & 3;
    const int r2 = (tid + 256) >> 2,  s2 = (tid + 256) & 3;
    const int8_t* A1 = A  + (size_t)(brow + r1) * HPAD + s1 * 16;
    const int8_t* A2 = A  + (size_t)(brow + r2) * HPAD + s2 * 16;
    const int8_t* B1 = Bw + (size_t)(bcol + r1) * HPAD + s1 * 16;
    const int8_t* B2 = Bw + (size_t)(bcol + r2) * HPAD + s2 * 16;
    const uint32_t dA1 = r1 * RS + s1 * 16, dA2 = r2 * RS + s2 * 16;

    const int aj = lane & 7, asel = lane >> 3;
    const uint32_t a_off = (uint32_t)((wm * 64 + aj + (asel & 1) * 8) * RS + (asel >> 1) * 16);
    const uint32_t b_off = (uint32_t)((wn * 32 + aj + (asel >> 1) * 8) * RS + (asel & 1) * 16);

    int acc[4][4][4];
#pragma unroll
    for (int i = 0; i < 4; i++)
#pragma unroll
        for (int j = 0; j < 4; j++)
#pragma unroll
            for (int q = 0; q < 4; q++) acc[i][j][q] = 0;

#pragma unroll
    for (int s = 0; s < 2; s++) {
        uint32_t sa = sbase + s * STGB, sb = sa + 10240;
        CP16(sa + dA1, A1 + s * 64); CP16(sa + dA2, A2 + s * 64);
        CP16(sb + dA1, B1 + s * 64); CP16(sb + dA2, B2 + s * 64);
        CPCOMMIT();
    }

    int st = 0, stn = 2;
    for (int it = 0; it < NC; it++) {
        CPWAIT1();
        __syncthreads();
        if (it + 2 < NC) {
            uint32_t sa = sbase + stn * STGB, sb = sa + 10240;
            const int c = (it + 2) * 64;
            CP16(sa + dA1, A1 + c); CP16(sa + dA2, A2 + c);
            CP16(sb + dA1, B1 + c); CP16(sb + dA2, B2 + c);
        }
        CPCOMMIT();

        const uint32_t ab = sbase + st * STGB, bb = ab + 10240;
#pragma unroll
        for (int ks = 0; ks < 2; ks++) {
            uint32_t bfr[2][4];
#pragma unroll
            for (int p = 0; p < 2; p++)
                ldm_x4(bfr[p], bb + b_off + p * 16 * RS + ks * 32);
#pragma unroll
            for (int mf = 0; mf < 4; mf++) {
                uint32_t afr[4];
                ldm_x4(afr, ab + a_off + mf * 16 * RS + ks * 32);
#pragma unroll
                for (int nf = 0; nf < 4; nf++)
                    mma_s8(acc[mf][nf], afr,
                           bfr[nf >> 1][(nf & 1) * 2], bfr[nf >> 1][(nf & 1) * 2 + 1]);
            }
        }
        if (++st == 3) st = 0;
        if (++stn == 3) stn = 0;
    }

    const float alpha = d_scales[sW] * d_scales[sA];
    double mysum = 0.0;
#pragma unroll
    for (int mf = 0; mf < 4; mf++) {
        const int m0 = brow + wm * 64 + mf * 16 + (lane >> 2);
#pragma unroll
        for (int nf = 0; nf < 4; nf++) {
            const int n = bcol + wn * 32 + nf * 8 + 2 * (lane & 3);
            const bool v0 = (n < HDIM), v1 = (n + 1 < HDIM);
            const float bv0 = v0 ? bias[n] : 0.f;
            const float bv1 = v1 ? bias[n + 1] : 0.f;
            float p00 = fmaf(alpha, (float)acc[mf][nf][0], bv0);
            float p01 = fmaf(alpha, (float)acc[mf][nf][1], bv1);
            float p10 = fmaf(alpha, (float)acc[mf][nf][2], bv0);
            float p11 = fmaf(alpha, (float)acc[mf][nf][3], bv1);
            float h00 = (v0 && p00 > 0.f) ? p00 : 0.f;
            float h01 = (v1 && p01 > 0.f) ? p01 : 0.f;
            float h10 = (v0 && p10 > 0.f) ? p10 : 0.f;
            float h11 = (v1 && p11 > 0.f) ? p11 : 0.f;
            mysum += (double)h00 + (double)h01 + (double)h10 + (double)h11;
            if (stepOut) {
                *(uchar2*)&stepOut[(size_t)m0 * HPAD + n] =
                    make_uchar2(h00 > 0.f ? 1 : 0, h01 > 0.f ? 1 : 0);
                *(uchar2*)&stepOut[(size_t)(m0 + 8) * HPAD + n] =
                    make_uchar2(h10 > 0.f ? 1 : 0, h11 > 0.f ? 1 : 0);
            }
            if (h4Out && v0) {
                *(float2*)&h4Out[(size_t)m0 * HDIM + n] = make_float2(h00, h01);
                *(float2*)&h4Out[(size_t)(m0 + 8) * HDIM + n] = make_float2(h10, h11);
            }
        }
    }
    smr[tid] = mysum;
    __syncthreads();
    for (int o = 128; o > 0; o >>= 1) {
        if (tid < o) smr[tid] += smr[tid + o];
        __syncthreads();
    }
    if (tid == 0 && slot >= 0)
        d_partials[slot][blockIdx.y * gridDim.x + blockIdx.x] = smr[0];
}

// ===========================================================================
// Final fp32 layer (N=10)
// ===========================================================================
__global__ void __launch_bounds__(256)
fc_out(const float* __restrict__ H4, const float* __restrict__ W5,
       const float* __restrict__ b5, float* __restrict__ out)
{
    int warp = (blockIdx.x * blockDim.x + threadIdx.x) >> 5;
    int lane = threadIdx.x & 31;
    if (warp >= B_ROWS) return;
    const float* h = H4 + (long)warp * HDIM;
    float acc[10];
#pragma unroll
    for (int j = 0; j < 10; j++) acc[j] = 0.f;
    for (int k = lane; k < HDIM; k += 32) {
        float hv = h[k];
#pragma unroll
        for (int j = 0; j < 10; j++)
            acc[j] = fmaf(hv, W5[j * HDIM + k], acc[j]);
    }
#pragma unroll
    for (int j = 0; j < 10; j++)
#pragma unroll
        for (int o = 16; o > 0; o >>= 1)
            acc[j] += __shfl_down_sync(0xffffffffu, acc[j], o);
    if (lane == 0)
#pragma unroll
        for (int j = 0; j < 10; j++)
            out[(long)warp * 10 + j] = acc[j] + b5[j];
}

// ===========================================================================
extern "C" void kernel_launch(void* const* d_in, const int* in_sizes, int n_in,
                              void* d_out, int out_size)
{
    const float* x  = (const float*)d_in[0];
    const float* W1 = (const float*)d_in[1];
    const float* b1 = (const float*)d_in[2];
    const float* W2 = (const float*)d_in[3];
    const float* b2 = (const float*)d_in[4];
    const float* W3 = (const float*)d_in[5];
    const float* b3 = (const float*)d_in[6];
    const float* W4 = (const float*)d_in[7];
    const float* b4 = (const float*)d_in[8];
    const float* W5 = (const float*)d_in[9];
    const float* b5 = (const float*)d_in[10];
    float* out = (float*)d_out;

    __nv_bfloat16 *xs, *sw1;
    int8_t *sw2, *sw3, *sw4, *stA, *stB;
    float* h4;
    cudaGetSymbolAddress((void**)&xs,  g_xs);
    cudaGetSymbolAddress((void**)&sw1, g_sw1);
    cudaGetSymbolAddress((void**)&sw2, g_sw2);
    cudaGetSymbolAddress((void**)&sw3, g_sw3);
    cudaGetSymbolAddress((void**)&sw4, g_sw4);
    cudaGetSymbolAddress((void**)&stA, g_stepA);
    cudaGetSymbolAddress((void**)&stB, g_stepB);
    cudaGetSymbolAddress((void**)&h4,  g_h4);

    cudaFuncSetAttribute(gemm_l1, cudaFuncAttributeMaxDynamicSharedMemorySize, SMEM_DYN);
    cudaFuncSetAttribute(gemm_s8, cudaFuncAttributeMaxDynamicSharedMemorySize, SMEM_DYN);

    const long nW1 = (long)HDIM * DIN;
    const long nW  = (long)HDIM * HDIM;
    const double invH = 1.0 / ((double)B_ROWS * HDIM);

    reduce_abs_partial<<<RED_BLOCKS, RED_THREADS>>>(W1, nW1, 0);
    reduce_finalize<<<1, 512>>>(0, 1.0 / (double)nW1, RED_BLOCKS);
    reduce_abs_partial<<<RED_BLOCKS, RED_THREADS>>>(W2, nW, 1);
    reduce_finalize<<<1, 512>>>(1, 1.0 / (double)nW, RED_BLOCKS);
    reduce_abs_partial<<<RED_BLOCKS, RED_THREADS>>>(W3, nW, 2);
    reduce_finalize<<<1, 512>>>(2, 1.0 / (double)nW, RED_BLOCKS);
    reduce_abs_partial<<<RED_BLOCKS, RED_THREADS>>>(W4, nW, 3);
    reduce_finalize<<<1, 512>>>(3, 1.0 / (double)nW, RED_BLOCKS);

    k_split_x<<<(int)(((long)B_ROWS * DIN / 4 + 255) / 256), 256>>>(x);
    k_sign_w1<<<(int)(((long)HPAD * K1PAD / 2 + 255) / 256), 256>>>(W1);
    k_sign_w_s8<<<(int)(((long)HPAD * HPAD / 4 + 255) / 256), 256>>>(W2, sw2);
    k_sign_w_s8<<<(int)(((long)HPAD * HPAD / 4 + 255) / 256), 256>>>(W3, sw3);
    k_sign_w_s8<<<(int)(((long)HPAD * HPAD / 4 + 255) / 256), 256>>>(W4, sw4);

    dim3 grid(HPAD / 128, B_ROWS / 128);   // (16, 64)

    gemm_l1<<<grid, 256, SMEM_DYN>>>(xs, sw1, b1, stA, 0, 4);
    reduce_finalize<<<1, 512>>>(4, invH, GPARTS);
    gemm_s8<<<grid, 256, SMEM_DYN>>>(stA, sw2, b2, stB, nullptr, 4, 1, 5);
    reduce_finalize<<<1, 512>>>(5, invH, GPARTS);
    gemm_s8<<<grid, 256, SMEM_DYN>>>(stB, sw3, b3, stA, nullptr, 5, 2, 6);
    reduce_finalize<<<1, 512>>>(6, invH, GPARTS);
    gemm_s8<<<grid, 256, SMEM_DYN>>>(stA, sw4, b4, nullptr, h4, 6, 3, -1);

    fc_out<<<(B_ROWS * 32) / 256, 256>>>(h4, W5, b5, out);

    (void)in_sizes; (void)n_in; (void)out_size;
}